// round 17
// baseline (speedup 1.0000x reference)
#include <cuda_runtime.h>
#include <math.h>

// Problem constants (shapes fixed by the dataset)
#define BB 32
#define AA 3
#define HH 160
#define WW 160
#define HW 25600              // H*W
#define NCH 24                // A*8
#define NT 512                // number of targets
#define NUMCLS 3
#define CHUNKS 5              // chunks per conf plane
#define CHUNK4 1280           // float4s per chunk (256 thr * 5)
#define NBLK_SPARSE 6         // blockIdx 0..5: 1536 = NT*AA pairs, one per thread
#define NBLK_DENSE 480        // blockIdx 6..485: 96 planes * 5 chunks
#define NBLK_TOTAL (NBLK_DENSE + NBLK_SPARSE)
#define TOTAL_CONF 2457600.0  // B*A*H*W

// Global accumulators: ONE atomicAdd per block per counter, always issued by
// tid0 (same-address atomics serialize at the LTS atomic ALU; block-level
// fan-in of <=486 ops is cheap — R10 proved per-warp global fan-in is not,
// R13 proved same-address shared ATOMS fan-in is not either). Read + reset
// by the finalizing block each launch -> graph-replay safe.
// [0]=s2(conf), [1]=box, [2]=cls, [3]=corr, [4]=n
__device__ float g_acc[5] = {0.f, 0.f, 0.f, 0.f, 0.f};
__device__ int   g_count  = 0;

__device__ __forceinline__ float tanhf_approx(float x) {   // 1 MUFU op (sm_75+)
    float t;
    asm("tanh.approx.f32 %0, %1;" : "=f"(t) : "f"(x));
    return t;
}

// sigmoid via tanh: 1 MUFU + 1 FMA
__device__ __forceinline__ float sig_t(float x) {
    return fmaf(tanhf_approx(x * 0.5f), 0.5f, 0.5f);
}

__device__ __forceinline__ float warpSum(float v) {
    #pragma unroll
    for (int o = 16; o > 0; o >>= 1) v += __shfl_down_sync(0xffffffffu, v, o);
    return v;
}

// fold 8 per-warp partials held in lanes 0..7 (zeros elsewhere): 3 shfl steps
__device__ __forceinline__ float warpSum8(float v) {
    v += __shfl_down_sync(0xffffffffu, v, 4);
    v += __shfl_down_sync(0xffffffffu, v, 2);
    v += __shfl_down_sync(0xffffffffu, v, 1);
    return v;
}

// sum of sigmoid(x)^2 over a float4, via sigma(x)^2 = 0.25*(1+tanh(x/2))^2
__device__ __forceinline__ float sumSq4(float4 v) {
    float t0 = tanhf_approx(v.x * 0.5f);
    float t1 = tanhf_approx(v.y * 0.5f);
    float t2 = tanhf_approx(v.z * 0.5f);
    float t3 = tanhf_approx(v.w * 0.5f);
    float u0 = 1.0f + t0, u1 = 1.0f + t1, u2 = 1.0f + t2, u3 = 1.0f + t3;
    float acc = (0.25f * u0) * u0;
    acc = fmaf(0.25f * u1, u1, acc);
    acc = fmaf(0.25f * u2, u2, acc);
    acc = fmaf(0.25f * u3, u3, acc);
    return acc;
}

__global__ __launch_bounds__(256) void loss_fused(const float* __restrict__ pred,
                                                  const float* __restrict__ targets,
                                                  float* __restrict__ out) {
    const int tid  = threadIdx.x;
    const int lane = tid & 31;
    const int warp = tid >> 5;
    __shared__ float sh[8];

    if (blockIdx.x < NBLK_SPARSE) {
        // ---- Sparse pass FIRST: exactly one (target, anchor) pair per thread ----
        const int sp   = blockIdx.x;                    // 0..5
        const int pair = sp * 256 + tid;                // 0..1535
        const int i    = pair & 511;                    // target index (coalesced)
        const int a    = pair >> 9;                     // anchor 0..2

        float box = 0.0f, cls = 0.0f, corr = 0.0f, n = 0.0f;

        const float* t = targets + i * 6;
        const int   b  = (int)t[0];
        const int   c  = (int)t[1];
        const float tx = t[2], ty = t[3], tw = t[4], th = t[5];
        const int gx = (int)(tx * (float)WW);
        const int gy = (int)(ty * (float)HH);
        if (gx >= 0 && gx < WW && gy >= 0 && gy < HH) {
            const int hw = gy * WW + gx;
            const float* p = pred + (size_t)(b * NCH + a * 8) * HW + hw;
            // 8 independent scattered loads (MLP=8, single DRAM batch)
            const float x0 = p[0];
            const float x1 = p[HW];
            const float x2 = p[2 * HW];
            const float x3 = p[3 * HW];
            const float x4 = p[4 * HW];
            const float x5 = p[5 * HW];
            const float x6 = p[6 * HW];
            const float x7 = p[7 * HW];

            float d;
            d = sig_t(x0) - tx;  box = fmaf(d, d, box);
            d = sig_t(x1) - ty;  box = fmaf(d, d, box);
            d = __expf(x2) - tw; box = fmaf(d, d, box);
            d = __expf(x3) - th; box = fmaf(d, d, box);
            // (s-1)^2 - s^2 = 1 - 2*sigma(x4) = -tanh(x4/2)
            corr = -tanhf_approx(x4 * 0.5f);
            d = sig_t(x5) - ((c == 0) ? 1.0f : 0.0f); cls = fmaf(d, d, cls);
            d = sig_t(x6) - ((c == 1) ? 1.0f : 0.0f); cls = fmaf(d, d, cls);
            d = sig_t(x7) - ((c == 2) ? 1.0f : 0.0f); cls = fmaf(d, d, cls);
            n = 1.0f;
        }

        __shared__ float sb[8], sc[8], sr[8], sn[8];
        box = warpSum(box); cls = warpSum(cls); corr = warpSum(corr); n = warpSum(n);
        if (lane == 0) { sb[warp] = box; sc[warp] = cls; sr[warp] = corr; sn[warp] = n; }
        __syncthreads();
        if (warp == 0) {
            float vb = (lane < 8) ? sb[lane] : 0.0f;
            float vc = (lane < 8) ? sc[lane] : 0.0f;
            float vr = (lane < 8) ? sr[lane] : 0.0f;
            float vn = (lane < 8) ? sn[lane] : 0.0f;
            vb = warpSum8(vb); vc = warpSum8(vc); vr = warpSum8(vr); vn = warpSum8(vn);
            if (lane == 0) {   // lane0 of warp0 == tid0
                atomicAdd(&g_acc[1], vb);
                atomicAdd(&g_acc[2], vc);
                atomicAdd(&g_acc[3], vr);
                atomicAdd(&g_acc[4], vn);
            }
        }
    } else {
        // ---- Dense conf pass: 5 straight-line float4 loads, tanh-based sigmoid^2 ----
        const int d     = blockIdx.x - NBLK_SPARSE;        // 0..479
        const int plane = d / CHUNKS;                      // 0..95 (b*3+a)
        const int chunk = d - plane * CHUNKS;              // 0..4
        // conf channel of plane p=(b*3+a) is flat plane index p*8+4
        const float4* base = reinterpret_cast<const float4*>(
            pred + (size_t)(plane * 8 + 4) * HW) + chunk * CHUNK4 + tid;

        const float4 v0 = base[0];
        const float4 v1 = base[256];
        const float4 v2 = base[512];
        const float4 v3 = base[768];
        const float4 v4 = base[1024];

        float acc = sumSq4(v0);
        acc += sumSq4(v1);
        acc += sumSq4(v2);
        acc += sumSq4(v3);
        acc += sumSq4(v4);

        float w = warpSum(acc);
        if (lane == 0) sh[warp] = w;
        __syncthreads();
        if (warp == 0) {
            float t = (lane < 8) ? sh[lane] : 0.0f;
            t = warpSum8(t);
            if (lane == 0) atomicAdd(&g_acc[0], t);   // tid0: ONE atomic per block
        }
    }

    // ---- Last-block-standing finalize. No second barrier needed: every
    // global side-effect above was issued by tid0 itself (lane0 of warp0),
    // so tid0's program order gives atomic -> release fence -> ticket.
    if (tid == 0) {
        __threadfence();                       // release: publish this block's atomics
        int ticket = atomicAdd(&g_count, 1);

        if (ticket == NBLK_TOTAL - 1) {
            __threadfence();                   // acquire: all accumulators visible

            const double s2   = (double)g_acc[0];
            const double box  = (double)g_acc[1];
            const double cls  = (double)g_acc[2];
            const double corr = (double)g_acc[3];
            const double n    = (double)g_acc[4];

            const double loss_conf = (s2 + corr) / TOTAL_CONF;
            const double loss_box  = box / (n * 4.0);
            const double loss_cls  = cls / (n * (double)NUMCLS);
            out[0] = (float)(5.0 * loss_box + loss_conf + loss_cls);

            // reset for next graph replay
            g_acc[0] = 0.0f; g_acc[1] = 0.0f; g_acc[2] = 0.0f;
            g_acc[3] = 0.0f; g_acc[4] = 0.0f;
            g_count = 0;
        }
    }
}

extern "C" void kernel_launch(void* const* d_in, const int* in_sizes, int n_in,
                              void* d_out, int out_size) {
    const float* pred    = (const float*)d_in[0];
    const float* targets = (const float*)d_in[1];
    float* out = (float*)d_out;

    loss_fused<<<NBLK_TOTAL, 256>>>(pred, targets, out);
}